// round 7
// baseline (speedup 1.0000x reference)
#include <cuda_runtime.h>

// rho' = L rho L^T,  L = A (x) B (x) C  (flat = r*64 + c*4 + j; r,c in [0,16),
// j in [0,4)).  A,B identity outside 0..3 -> independent row classes:
//   D  : {r<4,c<4}  64 rows          -> 16 blocks (64 rows x 64 cols)
//   Bc : {r>=4,c<4} 12 x 16 rows     -> 48 blocks (16 rows x 256 cols)
//   Cc : {r<4,c>=4} 12 x 16 rows     -> 48 blocks
//   Am : {r>=4,c>=4} 36 x 16 rows    -> 144 blocks
// Column-side C (j'-quads = one float4) and B (c'<4 = 4 consecutive float4s)
// are applied IN REGISTERS at load/store. Am blocks with chunk!=0 need no
// smem tile at all (row C = quad in regs, col B = 4-adjacent-lane shuffles):
// LDG -> 1 sync -> regs -> STG.  Col A (cols 0..255) is a smem stage for
// chunk==0 blocks only.  Each element read once, written once, coalesced.

__device__ __forceinline__ void mix4s(float* p, const int st, const float* M)
{
    float v0 = p[0], v1 = p[st], v2 = p[2*st], v3 = p[3*st];
    p[0]    = M[0] *v0 + M[1] *v1 + M[2] *v2 + M[3] *v3;
    p[st]   = M[4] *v0 + M[5] *v1 + M[6] *v2 + M[7] *v3;
    p[2*st] = M[8] *v0 + M[9] *v1 + M[10]*v2 + M[11]*v3;
    p[3*st] = M[12]*v0 + M[13]*v1 + M[14]*v2 + M[15]*v3;
}

__device__ __forceinline__ void mix4r(float* v, const int st, const float* M)
{
    float v0 = v[0], v1 = v[st], v2 = v[2*st], v3 = v[3*st];
    v[0]    = M[0] *v0 + M[1] *v1 + M[2] *v2 + M[3] *v3;
    v[st]   = M[4] *v0 + M[5] *v1 + M[6] *v2 + M[7] *v3;
    v[2*st] = M[8] *v0 + M[9] *v1 + M[10]*v2 + M[11]*v3;
    v[3*st] = M[12]*v0 + M[13]*v1 + M[14]*v2 + M[15]*v3;
}

// out[j] = sum_k M[j][k] v[k] within one float4 (the j'-quad)
__device__ __forceinline__ float4 mixf4(float4 v, const float* M)
{
    float4 r;
    r.x = M[0] *v.x + M[1] *v.y + M[2] *v.z + M[3] *v.w;
    r.y = M[4] *v.x + M[5] *v.y + M[6] *v.z + M[7] *v.w;
    r.z = M[8] *v.x + M[9] *v.y + M[10]*v.z + M[11]*v.w;
    r.w = M[12]*v.x + M[13]*v.y + M[14]*v.z + M[15]*v.w;
    return r;
}

// componentwise across the 4 float4s: y[i].c = sum_k M[i][k] y_old[k].c
__device__ __forceinline__ void mixquad(float4* y, const float* M)
{
    float4 v0 = y[0], v1 = y[1], v2 = y[2], v3 = y[3];
#define MQ(c) \
    y[0].c = M[0] *v0.c + M[1] *v1.c + M[2] *v2.c + M[3] *v3.c; \
    y[1].c = M[4] *v0.c + M[5] *v1.c + M[6] *v2.c + M[7] *v3.c; \
    y[2].c = M[8] *v0.c + M[9] *v1.c + M[10]*v2.c + M[11]*v3.c; \
    y[3].c = M[12]*v0.c + M[13]*v1.c + M[14]*v2.c + M[15]*v3.c;
    MQ(x) MQ(y) MQ(z) MQ(w)
#undef MQ
}

__global__ __launch_bounds__(256)
void rbs_fused(const float* __restrict__ in, float* __restrict__ out,
               const float* __restrict__ thetas)
{
    __shared__ float s[5120];     // D: 64 rows x 80 ; generic: 16 rows x 320
    __shared__ float sM[3][16];   // 0:A (row gates), 1:B (col), 2:C (ch)

    const int t = threadIdx.x;
    const int b = blockIdx.x;

    // ---- build the three 4x4 Givens products ----
    if (t < 3) {
        float M[16] = {1,0,0,0, 0,1,0,0, 0,0,1,0, 0,0,0,1};
        const int pi[6] = {0,0,0,1,1,2};
        const int pj[6] = {1,2,3,2,3,3};
#pragma unroll
        for (int g = 0; g < 6; ++g) {
            float th = thetas[t * 6 + g];
            float cc = cosf(th), sn = sinf(th);
            int i = pi[g], j = pj[g];
#pragma unroll
            for (int k = 0; k < 4; ++k) {
                float ai = M[i*4 + k], aj = M[j*4 + k];
                M[i*4 + k] =  cc * ai + sn * aj;   // M <- G * M
                M[j*4 + k] = -sn * ai + cc * aj;
            }
        }
#pragma unroll
        for (int k = 0; k < 16; ++k) sM[t][k] = M[k];
    }

    const float4* in4  = reinterpret_cast<const float4*>(in);
    float4*       out4 = reinterpret_cast<float4*>(out);

    // ---------------- decode block ----------------
    if (b >= 112 && ((b - 112) & 3) != 0) {
        // ========== FAST PATH: Am rows, chunk != 0 (108 blocks) ============
        // rows l = 0..15 -> grow = rb_r*64 + rb_c0*4 + l ; row mix = C only.
        const int id = b - 112, chunk = id & 3, g = id >> 2;
        const int rowbase = (4 + g / 3) * 64 + (4 + (g % 3) * 4) * 4;
        const int rq = t >> 6, fc = t & 63;         // row-quad, float4-col
        const int lane = t & 31;

        float4 y[4];
#pragma unroll
        for (int k = 0; k < 4; ++k)
            y[k] = in4[(rowbase + rq*4 + k) * 256 + chunk*64 + fc];

        __syncthreads();                            // sM ready
        float C4[16], B4[16];
#pragma unroll
        for (int k = 0; k < 16; ++k) { C4[k] = sM[2][k]; B4[k] = sM[1][k]; }

        // row C: across the 4 rows (j = k), componentwise
        mixquad(y, C4);

        // col B: c' = fc&15 < 4 -> mix across 4 adjacent lanes via shuffle
        {
            const int cpr  = fc & 15;
            const int base = lane & ~3;             // lanes 16a+c' -> 16a
            const bool doB = (cpr < 4);
            float br0 = B4[cpr*4+0], br1 = B4[cpr*4+1],
                  br2 = B4[cpr*4+2], br3 = B4[cpr*4+3];
#pragma unroll
            for (int k = 0; k < 4; ++k) {
                float* f = reinterpret_cast<float*>(&y[k]);
#pragma unroll
                for (int c = 0; c < 4; ++c) {
                    float v  = f[c];
                    float s0 = __shfl_sync(0xffffffffu, v, base + 0);
                    float s1 = __shfl_sync(0xffffffffu, v, base + 1);
                    float s2 = __shfl_sync(0xffffffffu, v, base + 2);
                    float s3 = __shfl_sync(0xffffffffu, v, base + 3);
                    if (doB) f[c] = br0*s0 + br1*s1 + br2*s2 + br3*s3;
                }
            }
        }

        // col C within each float4, then store
#pragma unroll
        for (int k = 0; k < 4; ++k)
            out4[(rowbase + rq*4 + k) * 256 + chunk*64 + fc] = mixf4(y[k], C4);

    } else if (b >= 16) {
        // ========== GENERIC 16-ROW PATH (Bc, Cc, Am-chunk0) ================
        int typ, chunk, rb_r = 0, rb_c = 0, rb_c0 = 0;
        if (b < 64)       { typ = 0; int id = b - 16;  chunk = id & 3; rb_r = 4 + (id >> 2); }
        else if (b < 112) { typ = 1; int id = b - 64;  chunk = id & 3; rb_c = 4 + (id >> 2); }
        else              { typ = 2; int id = b - 112; chunk = id & 3; int g = id >> 2;
                            rb_r = 4 + g / 3; rb_c0 = 4 + (g % 3) * 4; }

        const int l = t >> 4, m = t & 15;           // slot: row l, 16-float grp
        const int grow = (typ == 0) ? rb_r*64 + l
                       : (typ == 1) ? (l >> 2)*64 + rb_c*4 + (l & 3)
                                    : rb_r*64 + rb_c0*4 + l;
        // load raw -> smem (pad 4 per 16 floats; row stride 320)
        {
            float4 x[4];
#pragma unroll
            for (int k = 0; k < 4; ++k)
                x[k] = in4[grow*256 + chunk*64 + m*4 + k];
#pragma unroll
            for (int k = 0; k < 4; ++k)
                *reinterpret_cast<float4*>(&s[l*320 + m*20 + k*4]) = x[k];
        }
        __syncthreads();

        // row stage in registers: thread owns logical column t
        {
            float C4[16], M2[16];
            const float* msrc = (typ == 0) ? sM[1] : sM[0];
#pragma unroll
            for (int k = 0; k < 16; ++k) { C4[k] = sM[2][k]; M2[k] = msrc[k]; }
            const int pc = t + 4*(t >> 4);
            float v[16];
#pragma unroll
            for (int k = 0; k < 16; ++k) v[k] = s[k*320 + pc];
#pragma unroll
            for (int q = 0; q < 4; ++q) mix4r(&v[q*4], 1, C4);   // row C (j)
            if (typ != 2) {
#pragma unroll
                for (int j = 0; j < 4; ++j) mix4r(&v[j], 4, M2); // row B or A
            }
#pragma unroll
            for (int k = 0; k < 16; ++k) s[k*320 + pc] = v[k];
        }
        __syncthreads();

        // col A (rc'<4 = cols 0..255): chunk 0 only
        if (chunk == 0) {
            float A4[16];
#pragma unroll
            for (int k = 0; k < 16; ++k) A4[k] = sM[0][k];
#pragma unroll
            for (int h = 0; h < 4; ++h) {
                int g2 = t + 256*h;
                int l2 = g2 >> 6, c = g2 & 63;
                mix4s(&s[l2*320 + c + 4*(c >> 4)], 80, A4);
            }
            __syncthreads();
        }

        // store: col B (m&3==0) + col C in registers
        {
            float C4[16], B4[16];
#pragma unroll
            for (int k = 0; k < 16; ++k) { C4[k] = sM[2][k]; B4[k] = sM[1][k]; }
            float4 y[4];
#pragma unroll
            for (int k = 0; k < 4; ++k)
                y[k] = *reinterpret_cast<float4*>(&s[l*320 + m*20 + k*4]);
            if ((m & 3) == 0) mixquad(y, B4);
#pragma unroll
            for (int k = 0; k < 4; ++k)
                out4[grow*256 + chunk*64 + m*4 + k] = mixf4(y[k], C4);
        }

    } else {
        // ========== TYPE D: 64 rows {r<4,c<4} x 64 cols (16 blocks) ========
        const int ccq = b & 3, chunk = b >> 2;
        const int l = t >> 2, rcl = t & 3;          // slot: row l, rc'-strip
        const int grow = (l >> 4)*64 + (l & 15);
        const int gb = (chunk*4 + rcl)*16 + ccq*4;  // float4 base in row

        // load raw -> smem (row stride 80, pad 4 per 16)
        {
            float4 x[4];
#pragma unroll
            for (int w = 0; w < 4; ++w) x[w] = in4[grow*256 + gb + w];
#pragma unroll
            for (int w = 0; w < 4; ++w)
                *reinterpret_cast<float4*>(&s[l*80 + rcl*20 + w*4]) = x[w];
        }
        __syncthreads();

        // row C (j) + row B (cc) in registers: thread owns (rr, col)
        {
            float C4[16], B4[16];
#pragma unroll
            for (int k = 0; k < 16; ++k) { C4[k] = sM[2][k]; B4[k] = sM[1][k]; }
            const int rr = t >> 6, q = t & 63;
            const int pc = q + 4*(q >> 4);
            float v[16];
#pragma unroll
            for (int k = 0; k < 16; ++k) v[k] = s[(rr*16 + k)*80 + pc];
#pragma unroll
            for (int cc = 0; cc < 4; ++cc) mix4r(&v[cc*4], 1, C4);
#pragma unroll
            for (int j = 0; j < 4; ++j)    mix4r(&v[j], 4, B4);
#pragma unroll
            for (int k = 0; k < 16; ++k) s[(rr*16 + k)*80 + pc] = v[k];
        }
        __syncthreads();

        // row A across rr (stride 16 rows)
        {
            float A4[16];
#pragma unroll
            for (int k = 0; k < 16; ++k) A4[k] = sM[0][k];
#pragma unroll
            for (int h = 0; h < 4; ++h) {
                int g2 = t + 256*h;
                int ccj = g2 >> 6, q = g2 & 63;
                mix4s(&s[ccj*80 + q + 4*(q >> 4)], 16*80, A4);
            }
        }
        __syncthreads();

        // col A (across rcl strips): chunk 0 only
        if (chunk == 0) {
            float A4[16];
#pragma unroll
            for (int k = 0; k < 16; ++k) A4[k] = sM[0][k];
#pragma unroll
            for (int h = 0; h < 4; ++h) {
                int g2 = t + 256*h;
                int l2 = g2 >> 4, wj = g2 & 15;
                mix4s(&s[l2*80 + wj], 20, A4);
            }
            __syncthreads();
        }

        // store: col B (ccq==0) + col C in registers
        {
            float C4[16], B4[16];
#pragma unroll
            for (int k = 0; k < 16; ++k) { C4[k] = sM[2][k]; B4[k] = sM[1][k]; }
            float4 y[4];
#pragma unroll
            for (int w = 0; w < 4; ++w)
                y[w] = *reinterpret_cast<float4*>(&s[l*80 + rcl*20 + w*4]);
            if (ccq == 0) mixquad(y, B4);
#pragma unroll
            for (int w = 0; w < 4; ++w)
                out4[grow*256 + gb + w] = mixf4(y[w], C4);
        }
    }
}

extern "C" void kernel_launch(void* const* d_in, const int* in_sizes, int n_in,
                              void* d_out, int out_size)
{
    const float* state  = nullptr;
    const float* thetas = nullptr;
    for (int i = 0; i < n_in; ++i) {
        if (in_sizes[i] == 18 && !thetas)
            thetas = (const float*)d_in[i];
        else if (in_sizes[i] == 1024 * 1024 && !state)
            state = (const float*)d_in[i];
    }
    rbs_fused<<<256, 256>>>(state, (float*)d_out, thetas);
}